// round 16
// baseline (speedup 1.0000x reference)
#include <cuda_runtime.h>
#include <cuda_bf16.h>
#include <cstdint>
#include <math.h>

#define S      512
#define BATCH  64
#define TLEN   1024
#define OBS_N  32000
#define NTHREADS 512
#define NSM_CH 27               // expTq chunks resident in SMEM (of 32)
#define NRG_CH 5                // chunks resident in registers
#define LOG2E 1.4426950408889634f
#define LN2   0.6931471805599453f
#define L2Q   15.988707f        // log2(255*255)

// ---------------- device scratch ---------------------------------------------
__device__ float g_lseRow[S];
__device__ float g_mT[S];
__device__ float g_lseObs[S];
// quantized expT, chunked: addr = c*8192 + j*16 + b,  i = c*16 + b
__device__ unsigned char g_expTq[32 * 8192];

// ---------------- helpers -----------------------------------------------------
__device__ __forceinline__ float ex2_fast(float x) {   // MUFU.EX2
    float r;
    asm("ex2.approx.ftz.f32 %0, %1;" : "=f"(r) : "f"(x));
    return r;
}
__device__ __forceinline__ unsigned redux_max_u32(unsigned v) {
    unsigned r;
    asm("redux.sync.max.u32 %0, %1, 0xffffffff;" : "=r"(r) : "r"(v));
    return r;
}

template <int NW>
__device__ __forceinline__ float blkMax(float v, float* red) {
    #pragma unroll
    for (int o = 16; o > 0; o >>= 1) v = fmaxf(v, __shfl_xor_sync(0xffffffffu, v, o));
    int w = threadIdx.x >> 5;
    if ((threadIdx.x & 31) == 0) red[w] = v;
    __syncthreads();
    float m = red[0];
    #pragma unroll
    for (int k = 1; k < NW; ++k) m = fmaxf(m, red[k]);
    __syncthreads();
    return m;
}
template <int NW>
__device__ __forceinline__ float blkSum(float v, float* red) {
    #pragma unroll
    for (int o = 16; o > 0; o >>= 1) v += __shfl_xor_sync(0xffffffffu, v, o);
    int w = threadIdx.x >> 5;
    if ((threadIdx.x & 31) == 0) red[w] = v;
    __syncthreads();
    float m = 0.f;
    #pragma unroll
    for (int k = 0; k < NW; ++k) m += red[k];
    __syncthreads();
    return m;
}

// ---------------- precompute (3 launches; k_forward = my launch #4) ------------
__global__ void k_rowlse(const float* __restrict__ ST) {
    __shared__ float red[8];
    int i = blockIdx.x, t = threadIdx.x;
    float x0 = ST[i * S + t], x1 = ST[i * S + t + 256];
    float M = blkMax<8>(fmaxf(x0, x1), red);
    float Ssum = blkSum<8>(expf(x0 - M) + expf(x1 - M), red);
    if (t == 0) g_lseRow[i] = M + logf(Ssum);
}
__global__ void k_colmax(const float* __restrict__ ST) {
    int j = blockIdx.x * blockDim.x + threadIdx.x;
    float m = -1e30f;
    for (int i = 0; i < S; ++i) m = fmaxf(m, ST[i * S + j] - g_lseRow[i]);
    g_mT[j] = m;
}
__global__ void k_pre3(const float* __restrict__ ST, const float* __restrict__ OT) {
    __shared__ float red[8];
    int i = blockIdx.x, t = threadIdx.x;
    float l = g_lseRow[i];
    int c = i >> 4, b = i & 15;
    for (int j = t; j < S; j += 256) {
        float e = expf(ST[i * S + j] - l - g_mT[j]);
        unsigned q = __float2uint_rn(fminf(e, 1.f) * 255.f);
        g_expTq[c * 8192 + j * 16 + b] = (unsigned char)q;
    }
    const float* row = OT + (size_t)i * OBS_N;
    float m = -1e30f;
    for (int k = t; k < OBS_N; k += 256) m = fmaxf(m, row[k]);
    float M = blkMax<8>(m, red);
    float acc = 0.f;
    for (int k = t; k < OBS_N; k += 256) acc += expf(row[k] - M);
    float Ssum = blkSum<8>(acc, red);
    if (t == 0) g_lseObs[i] = M + logf(Ssum);
}

// ---------------- forward kernel ------------------------------------------------
// ONE CTA per batch, 512 threads, thread t <-> output state j = t. No cluster.
// expTq: 27 chunks in SMEM (216 KB) + 5 chunks in registers (step-invariant).
// Exponent groups: warp w covers j,i in [32w, 32w+32); chunk c -> group c>>1.
// Per step: matvec (27 LDS.128 + 5 reg, 128 dp4a into 16 group accumulators)
// -> exponent combine -> ex2 -> redux.max -> quantize u8 -> store byte + group
// exp -> one __syncthreads.
//
// SMEM (bytes):
//  [0,221184)        sTq   u8 [27 c][512 j][16 b]
//  [221184,222208)   sAqD  u8 [2 buf][512]
//  [222208,222336)   sEoD  u32 [2 buf][16]
//  [222336,226432)   sOb   int [1024]
//  [226432,226496)   sRed  f32 [16]
#define OFF_AQ   221184
#define OFF_EO   222208
#define OFF_OB   222336
#define OFF_RED  226432
#define SMEM_TOTAL 226496

__global__ void __launch_bounds__(NTHREADS, 1)
k_forward(const int* __restrict__ obs, const float* __restrict__ OT,
          const float* __restrict__ prior, float* __restrict__ out) {
    extern __shared__ char smem[];
    unsigned char* sTq  = reinterpret_cast<unsigned char*>(smem);
    unsigned char* sAqD = reinterpret_cast<unsigned char*>(smem + OFF_AQ);
    unsigned*      sEoD = reinterpret_cast<unsigned*>(smem + OFF_EO);
    int*           sOb  = reinterpret_cast<int*>(smem + OFF_OB);
    float*         sRed = reinterpret_cast<float*>(smem + OFF_RED);

    const int t   = threadIdx.x;          // == j
    const int b   = blockIdx.x;
    const int wid = t >> 5;

    // one-time SMEM fill: first 27 chunks
    {
        const uint4* src = reinterpret_cast<const uint4*>(g_expTq);
        uint4* dst = reinterpret_cast<uint4*>(sTq);
        for (int k = t; k < NSM_CH * 512; k += NTHREADS) dst[k] = src[k];
    }
    for (int k = t; k < TLEN; k += NTHREADS) sOb[k] = obs[b * TLEN + k];

    // register-resident chunks 27..31 (step-invariant, this thread's j only)
    uint4 eReg[NRG_CH];
    #pragma unroll
    for (int m = 0; m < NRG_CH; ++m)
        eReg[m] = *reinterpret_cast<const uint4*>(
            g_expTq + (size_t)(NSM_CH + m) * 8192 + t * 16);
    __syncthreads();

    // ---- init: prior log-softmax + alpha0, quantize, buf 0 ----
    float E2, rawOwn;
    const float cf = g_mT[t] - g_lseObs[t];
    {
        float p = prior[t];
        float Mp = blkMax<16>(p, sRed);
        float Sp = blkSum<16>(expf(p - Mp), sRed);
        float lseP = Mp + logf(Sp);
        int o0 = sOb[0];
        float a0 = __ldg(OT + (size_t)t * OBS_N + o0) + (p - lseP) - g_lseObs[t];
        float M = blkMax<16>(a0, sRed);
        E2 = M * LOG2E;
        rawOwn = fmaxf(ex2_fast((a0 - M) * LOG2E), 1e-35f);
        unsigned bexp = __float_as_uint(rawOwn) >> 23;
        unsigned bw = redux_max_u32(bexp);          // warp = group (32 j)
        float qsf = __uint_as_float((253u - bw) << 23) * 255.f;
        sAqD[t] = (unsigned char)__float2uint_rn(rawOwn * qsf);
        if ((t & 31) == 0) sEoD[wid] = bw;
    }
    __syncthreads();

    const float* wPtr = OT + (size_t)t * OBS_N;
    const uint4* ePtr = reinterpret_cast<const uint4*>(sTq + t * 16);

    #pragma unroll 1
    for (int step = 1; step <= TLEN; ++step) {
        const int ot = (step < TLEN) ? sOb[step] : 0;
        const float w = __ldg(wPtr + ot);           // hidden under matvec
        const int rbuf = (step - 1) & 1;

        // ---- matvec: 32 dp4a chunks into 16 group accumulators ----
        const uint4* aSrc = reinterpret_cast<const uint4*>(sAqD + rbuf * 512);
        unsigned acc[16];
        #pragma unroll
        for (int g = 0; g < 16; ++g) acc[g] = 0u;
        #pragma unroll
        for (int c = 0; c < NSM_CH; ++c) {
            uint4 av = aSrc[c];                     // broadcast
            uint4 ev = ePtr[c * 512];               // 8192-byte chunk stride
            unsigned a = acc[c >> 1];
            a = __dp4a(av.x, ev.x, a);
            a = __dp4a(av.y, ev.y, a);
            a = __dp4a(av.z, ev.z, a);
            a = __dp4a(av.w, ev.w, a);
            acc[c >> 1] = a;
        }
        #pragma unroll
        for (int m = 0; m < NRG_CH; ++m) {
            uint4 av = aSrc[NSM_CH + m];
            uint4 ev = eReg[m];
            unsigned a = acc[(NSM_CH + m) >> 1];
            a = __dp4a(av.x, ev.x, a);
            a = __dp4a(av.y, ev.y, a);
            a = __dp4a(av.z, ev.z, a);
            a = __dp4a(av.w, ev.w, a);
            acc[(NSM_CH + m) >> 1] = a;
        }

        // ---- combine with 16 group exponents ----
        unsigned be[16];
        {
            const uint4* eSrc = reinterpret_cast<const uint4*>(sEoD + rbuf * 16);
            #pragma unroll
            for (int g = 0; g < 4; ++g) {
                uint4 v = eSrc[g];                  // broadcast
                be[g * 4] = v.x; be[g * 4 + 1] = v.y;
                be[g * 4 + 2] = v.z; be[g * 4 + 3] = v.w;
            }
        }
        unsigned bref = be[0];
        #pragma unroll
        for (int g = 1; g < 16; ++g) bref = max(bref, be[g]);
        float P = 0.f;
        #pragma unroll
        for (int g = 0; g < 16; ++g) {
            int d = (int)be[g] - (int)bref;
            d = (d < -126) ? -126 : d;
            P += (float)acc[g] * __uint_as_float((unsigned)(d + 127) << 23);
        }
        E2 += (float)((int)bref - 126);

        // ---- raw alpha(step), quantize, publish ----
        float raw = fmaxf(P * ex2_fast(fmaf(w + cf, LOG2E, -L2Q)), 1e-35f);
        unsigned bexp = __float_as_uint(raw) >> 23;
        unsigned bw = redux_max_u32(bexp);
        float qsf = __uint_as_float((253u - bw) << 23) * 255.f;
        const int wbuf = step & 1;
        sAqD[wbuf * 512 + t] = (unsigned char)__float2uint_rn(raw * qsf);
        if ((t & 31) == 0) sEoD[wbuf * 16 + wid] = bw;
        rawOwn = raw;
        __syncthreads();
    }

    // ---- final: logsumexp over alpha ----
    float total = blkSum<16>(rawOwn, sRed);
    if (t == 0) out[b] = logf(total) + E2 * LN2;
}

// ---------------- launch -------------------------------------------------------
extern "C" void kernel_launch(void* const* d_in, const int* in_sizes, int n_in,
                              void* d_out, int out_size) {
    const int*   obs   = (const int*)d_in[0];
    const float* ST    = (const float*)d_in[1];
    const float* OT    = (const float*)d_in[2];
    const float* prior = (const float*)d_in[3];
    float* out = (float*)d_out;

    cudaFuncSetAttribute(k_forward, cudaFuncAttributeMaxDynamicSharedMemorySize,
                         SMEM_TOTAL);

    k_rowlse<<<S, 256>>>(ST);
    k_colmax<<<4, 128>>>(ST);
    k_pre3<<<S, 256>>>(ST, OT);
    k_forward<<<BATCH, NTHREADS, SMEM_TOTAL>>>(obs, OT, prior, out);
}

// round 17
// speedup vs baseline: 1.5927x; 1.5927x over previous
#include <cuda_runtime.h>
#include <cuda_bf16.h>
#include <cstdint>
#include <math.h>

#define S      512
#define BATCH  64
#define TLEN   1024
#define OBS_N  32000
#define NTHREADS 256
#define JH     256              // j-columns per CTA (cluster of 2)
#define LOG2E 1.4426950408889634f
#define LN2   0.6931471805599453f
#define L2Q   15.988707f        // log2(255*255)

// ---------------- device scratch ---------------------------------------------
__device__ float g_lseRow[S];
__device__ float g_mT[S];
__device__ float g_lseObs[S];
// quantized expT, per-rank copy with CTA-local i-chunk order:
// addr = rank*131072 + c*4096 + j_local*16 + b
//   c<16 : global i = rank*256     + 16*c      + b   (own half)
//   c>=16: global i = (1-rank)*256 + 16*(c-16) + b   (peer half)
__device__ unsigned char g_expTq[2 * 32 * 4096];

// ---------------- helpers -----------------------------------------------------
__device__ __forceinline__ float ex2_fast(float x) {   // MUFU.EX2
    float r;
    asm("ex2.approx.ftz.f32 %0, %1;" : "=f"(r) : "f"(x));
    return r;
}
__device__ __forceinline__ unsigned redux_max_u32(unsigned v) {
    unsigned r;
    asm("redux.sync.max.u32 %0, %1, 0xffffffff;" : "=r"(r) : "r"(v));
    return r;
}
__device__ __forceinline__ uint32_t smem_u32(const void* p) {
    uint32_t a;
    asm("{ .reg .u64 t; cvta.to.shared.u64 t, %1; cvt.u32.u64 %0, t; }"
        : "=r"(a) : "l"(p));
    return a;
}
__device__ __forceinline__ uint32_t mapa_u32(uint32_t a, uint32_t rank) {
    uint32_t d;
    asm("mapa.shared::cluster.u32 %0, %1, %2;" : "=r"(d) : "r"(a), "r"(rank));
    return d;
}
__device__ __forceinline__ void st_cluster_u8(uint32_t a, unsigned v) {
    asm volatile("st.shared::cluster.u8 [%0], %1;" :: "r"(a), "r"(v) : "memory");
}
__device__ __forceinline__ void st_cluster_u32(uint32_t a, unsigned v) {
    asm volatile("st.shared::cluster.u32 [%0], %1;" :: "r"(a), "r"(v) : "memory");
}
__device__ __forceinline__ void mbar_init(uint32_t a, unsigned cnt) {
    asm volatile("mbarrier.init.shared.b64 [%0], %1;" :: "r"(a), "r"(cnt) : "memory");
}
__device__ __forceinline__ void mbar_arrive_cluster(uint32_t a) {
    asm volatile("mbarrier.arrive.release.cluster.shared::cluster.b64 _, [%0];"
                 :: "r"(a) : "memory");
}
__device__ __forceinline__ void mbar_wait_cluster(uint32_t a, unsigned parity) {
    unsigned done;
    asm volatile(
        "{\n\t.reg .pred p;\n\t"
        "mbarrier.try_wait.parity.acquire.cluster.shared::cta.b64 p, [%1], %2;\n\t"
        "selp.b32 %0, 1, 0, p;\n\t}"
        : "=r"(done) : "r"(a), "r"(parity) : "memory");
    if (!done) {
        asm volatile(
            "{\n\t.reg .pred P1;\n\t"
            "WAIT_LOOP_%=:\n\t"
            "mbarrier.try_wait.parity.acquire.cluster.shared::cta.b64 P1, [%0], %1, 0x989680;\n\t"
            "@P1 bra.uni WAIT_DONE_%=;\n\t"
            "bra.uni WAIT_LOOP_%=;\n\t"
            "WAIT_DONE_%=:\n\t}"
            :: "r"(a), "r"(parity) : "memory");
    }
}
#define CLUSTER_SYNC() do { \
    asm volatile("barrier.cluster.arrive.aligned;" ::: "memory"); \
    asm volatile("barrier.cluster.wait.aligned;"   ::: "memory"); \
} while (0)

template <int NW>
__device__ __forceinline__ float blkMax(float v, float* red) {
    #pragma unroll
    for (int o = 16; o > 0; o >>= 1) v = fmaxf(v, __shfl_xor_sync(0xffffffffu, v, o));
    int w = threadIdx.x >> 5;
    if ((threadIdx.x & 31) == 0) red[w] = v;
    __syncthreads();
    float m = red[0];
    #pragma unroll
    for (int k = 1; k < NW; ++k) m = fmaxf(m, red[k]);
    __syncthreads();
    return m;
}
template <int NW>
__device__ __forceinline__ float blkSum(float v, float* red) {
    #pragma unroll
    for (int o = 16; o > 0; o >>= 1) v += __shfl_xor_sync(0xffffffffu, v, o);
    int w = threadIdx.x >> 5;
    if ((threadIdx.x & 31) == 0) red[w] = v;
    __syncthreads();
    float m = 0.f;
    #pragma unroll
    for (int k = 0; k < NW; ++k) m += red[k];
    __syncthreads();
    return m;
}

// ---------------- precompute (3 launches; k_forward = my launch #4) ------------
__global__ void k_rowlse(const float* __restrict__ ST) {
    __shared__ float red[8];
    int i = blockIdx.x, t = threadIdx.x;
    float x0 = ST[i * S + t], x1 = ST[i * S + t + 256];
    float M = blkMax<8>(fmaxf(x0, x1), red);
    float Ssum = blkSum<8>(expf(x0 - M) + expf(x1 - M), red);
    if (t == 0) g_lseRow[i] = M + logf(Ssum);
}
__global__ void k_colmax(const float* __restrict__ ST) {
    int j = blockIdx.x * blockDim.x + threadIdx.x;
    float m = -1e30f;
    for (int i = 0; i < S; ++i) m = fmaxf(m, ST[i * S + j] - g_lseRow[i]);
    g_mT[j] = m;
}
__global__ void k_pre3(const float* __restrict__ ST, const float* __restrict__ OT) {
    __shared__ float red[8];
    int i = blockIdx.x, t = threadIdx.x;
    float l = g_lseRow[i];
    for (int j = t; j < S; j += 256) {
        float e = expf(ST[i * S + j] - l - g_mT[j]);
        unsigned q = __float2uint_rn(fminf(e, 1.f) * 255.f);
        int r = j >> 8, jl = j & 255;
        int ihalf = i >> 8, il = i & 255;
        int c = ((ihalf == r) ? 0 : 16) + (il >> 4);
        int b = il & 15;
        g_expTq[r * 131072 + c * 4096 + jl * 16 + b] = (unsigned char)q;
    }
    const float* row = OT + (size_t)i * OBS_N;
    float m = -1e30f;
    for (int k = t; k < OBS_N; k += 256) m = fmaxf(m, row[k]);
    float M = blkMax<8>(m, red);
    float acc = 0.f;
    for (int k = t; k < OBS_N; k += 256) acc += expf(row[k] - M);
    float Ssum = blkSum<8>(acc, red);
    if (t == 0) g_lseObs[i] = M + logf(Ssum);
}

// ---------------- forward kernel ------------------------------------------------
// 256 threads, cluster of 2 (j-split), thread t <-> j_local t.
// ALL 32 expTq chunks live in registers (uint4 eReg[32] = 128 regs,
// step-invariant) — zero LDS crossbar traffic for the e-operand.
// Per step: wait(exch k-1) -> 32 dp4a chunks (alpha bytes: own from sAqD
// broadcast, peer straight from recv slot) -> combine via 16 per-warp
// exponents -> ex2 -> redux.max -> quantize -> ship u8+exps -> arrive -> sync.
//
// SMEM (bytes):
//  [0,512)      sAqD   u8 [2 buf][256]
//  [512,576)    sEoD   u32 [2 buf][8]
//  [576,1152)   sRecvQ [2 slot][288]: u8 q[256] + u32 exps[8]
//  [1152,5248)  sOb    int [1024]
//  [5248,5280)  sRed   f32 [8]
//  [5280,5296)  mbar   2 x u64
#define OFF_AQ   0
#define OFF_EO   512
#define OFF_RQ   576
#define OFF_OB   1152
#define OFF_RED  5248
#define OFF_MB   5280
#define SMEM_TOTAL 5376
#define RQ_STRIDE 288

__global__ void __launch_bounds__(NTHREADS, 1) __cluster_dims__(2, 1, 1)
k_forward(const int* __restrict__ obs, const float* __restrict__ OT,
          const float* __restrict__ prior, float* __restrict__ out) {
    extern __shared__ char smem[];
    unsigned char* sAqD  = reinterpret_cast<unsigned char*>(smem + OFF_AQ);
    unsigned*      sEoD  = reinterpret_cast<unsigned*>(smem + OFF_EO);
    unsigned char* sRecvQ= reinterpret_cast<unsigned char*>(smem + OFF_RQ);
    int*           sOb   = reinterpret_cast<int*>(smem + OFF_OB);
    float*         sRed  = reinterpret_cast<float*>(smem + OFF_RED);

    const int t    = threadIdx.x;
    const int rank = blockIdx.x & 1;
    const int b    = blockIdx.x >> 1;
    const int wid  = t >> 5;

    const uint32_t mbLoc  = smem_u32(smem + OFF_MB);
    const uint32_t mbPeer = mapa_u32(mbLoc, (uint32_t)(rank ^ 1));
    const uint32_t rqPeer = mapa_u32(smem_u32(sRecvQ), (uint32_t)(rank ^ 1));

    if (t == 0) { mbar_init(mbLoc, NTHREADS); mbar_init(mbLoc + 8, NTHREADS); }

    const int ownBase  = rank * JH;
    const int peerBase = (rank ^ 1) * JH;

    // this thread's full e-row, register-resident (step-invariant): 128 regs
    uint4 eReg[32];
    {
        const uint4* src = reinterpret_cast<const uint4*>(
            g_expTq + rank * 131072 + t * 16);
        #pragma unroll
        for (int c = 0; c < 32; ++c) eReg[c] = __ldg(src + c * 256);
    }
    for (int k = t; k < TLEN; k += NTHREADS) sOb[k] = obs[b * TLEN + k];
    __syncthreads();

    // ---- init: prior log-softmax (block-wide over 512), alpha0 own half ----
    float E2, rawOwn, cf;
    {
        float p0 = prior[ownBase + t], p1 = prior[peerBase + t];
        float Mp = blkMax<8>(fmaxf(p0, p1), sRed);
        float Sp = blkSum<8>(expf(p0 - Mp) + expf(p1 - Mp), sRed);
        float lseP = Mp + logf(Sp);
        float lo0 = g_lseObs[ownBase + t];
        cf = g_mT[ownBase + t] - lo0;

        int o0 = sOb[0];
        float aO = __ldg(OT + (size_t)(ownBase + t) * OBS_N + o0)
                   + (p0 - lseP) - lo0;
        float aP = __ldg(OT + (size_t)(peerBase + t) * OBS_N + o0)
                   + (p1 - lseP) - g_lseObs[peerBase + t];
        float M = blkMax<8>(fmaxf(aO, aP), sRed);   // cluster-consistent ref
        E2 = M * LOG2E;
        rawOwn = fmaxf(ex2_fast((aO - M) * LOG2E), 1e-35f);

        unsigned bexp = __float_as_uint(rawOwn) >> 23;
        unsigned bw = redux_max_u32(bexp);
        float qsf = __uint_as_float((253u - bw) << 23) * 255.f;
        unsigned q = __float2uint_rn(rawOwn * qsf);
        sAqD[t] = (unsigned char)q;
        st_cluster_u8(rqPeer + (unsigned)t, q);
        if ((t & 31) == 0) {
            sEoD[wid] = bw;
            st_cluster_u32(rqPeer + 256u + (unsigned)wid * 4u, bw);
        }
    }
    CLUSTER_SYNC();                      // peer mbar inits + init stores visible
    mbar_arrive_cluster(mbPeer);         // exchange 0 on slot 0
    __syncthreads();

    const float* wPtr = OT + (size_t)(ownBase + t) * OBS_N;
    int slot = 0;
    int ph0 = 0, ph1 = 0;

    #pragma unroll 1
    for (int step = 1; step <= TLEN; ++step) {
        const int ot = (step < TLEN) ? sOb[step] : 0;
        const float w = __ldg(wPtr + ot);      // hidden under wait+matvec

        // ---- wait exchange(step-1); acquire covers sRecvQ ----
        mbar_wait_cluster(mbLoc + slot * 8, (unsigned)(slot ? ph1 : ph0));
        if (slot) ph1 ^= 1; else ph0 ^= 1;
        const int rbuf = (step - 1) & 1;

        // ---- matvec: 32 dp4a chunks, e from registers ----
        unsigned acc[16];
        #pragma unroll
        for (int g = 0; g < 16; ++g) acc[g] = 0u;
        {
            const uint4* aOwn = reinterpret_cast<const uint4*>(sAqD + rbuf * 256);
            const uint4* aPr  = reinterpret_cast<const uint4*>(sRecvQ + slot * RQ_STRIDE);
            #pragma unroll
            for (int c = 0; c < 16; ++c) {
                uint4 av = aOwn[c];                 // broadcast LDS
                uint4 ev = eReg[c];
                unsigned a = acc[c >> 1];
                a = __dp4a(av.x, ev.x, a);
                a = __dp4a(av.y, ev.y, a);
                a = __dp4a(av.z, ev.z, a);
                a = __dp4a(av.w, ev.w, a);
                acc[c >> 1] = a;
            }
            #pragma unroll
            for (int c = 0; c < 16; ++c) {
                uint4 av = aPr[c];                  // broadcast LDS
                uint4 ev = eReg[16 + c];
                unsigned a = acc[8 + (c >> 1)];
                a = __dp4a(av.x, ev.x, a);
                a = __dp4a(av.y, ev.y, a);
                a = __dp4a(av.z, ev.z, a);
                a = __dp4a(av.w, ev.w, a);
                acc[8 + (c >> 1)] = a;
            }
        }

        // ---- combine with 16 per-warp exponents ----
        unsigned be[16];
        {
            const unsigned* eo = sEoD + rbuf * 8;
            const unsigned* ep = reinterpret_cast<const unsigned*>(
                sRecvQ + slot * RQ_STRIDE + 256);
            #pragma unroll
            for (int g = 0; g < 8; ++g) { be[g] = eo[g]; be[8 + g] = ep[g]; }
        }
        unsigned bref = be[0];
        #pragma unroll
        for (int g = 1; g < 16; ++g) bref = max(bref, be[g]);
        float P = 0.f;
        #pragma unroll
        for (int g = 0; g < 16; ++g) {
            int d = (int)be[g] - (int)bref;
            d = (d < -126) ? -126 : d;
            P += (float)acc[g] * __uint_as_float((unsigned)(d + 127) << 23);
        }
        E2 += (float)((int)bref - 126);

        // ---- raw alpha(step), quantize, ship exchange(step) ----
        float raw = fmaxf(P * ex2_fast(fmaf(w + cf, LOG2E, -L2Q)), 1e-35f);
        unsigned bexp = __float_as_uint(raw) >> 23;
        unsigned bw = redux_max_u32(bexp);
        float qsf = __uint_as_float((253u - bw) << 23) * 255.f;
        unsigned q = __float2uint_rn(raw * qsf);

        const int sendSlot = slot ^ 1;
        const int wbuf = step & 1;
        sAqD[wbuf * 256 + t] = (unsigned char)q;
        st_cluster_u8(rqPeer + (unsigned)(sendSlot * RQ_STRIDE + t), q);
        if ((t & 31) == 0) {
            sEoD[wbuf * 8 + wid] = bw;
            st_cluster_u32(rqPeer + (unsigned)(sendSlot * RQ_STRIDE + 256 + wid * 4), bw);
        }
        mbar_arrive_cluster(mbPeer + sendSlot * 8);
        rawOwn = raw;
        __syncthreads();                  // bounds skew for sAqD/sEoD reuse
        slot = sendSlot;
    }

    // ---- final: own raw + dequantized peer raw (exchange TLEN pending) ----
    mbar_wait_cluster(mbLoc + slot * 8, (unsigned)(slot ? ph1 : ph0));
    float peerVal;
    {
        unsigned qp = (unsigned)sRecvQ[slot * RQ_STRIDE + t];
        unsigned beg = reinterpret_cast<const unsigned*>(
            sRecvQ + slot * RQ_STRIDE + 256)[wid];
        peerVal = (float)qp * __uint_as_float((beg + 1u) << 23) * (1.f / 255.f);
    }
    float total = blkSum<8>(rawOwn + peerVal, sRed);
    if (rank == 0 && t == 0) out[b] = logf(total) + E2 * LN2;
    CLUSTER_SYNC();
}

// ---------------- launch -------------------------------------------------------
extern "C" void kernel_launch(void* const* d_in, const int* in_sizes, int n_in,
                              void* d_out, int out_size) {
    const int*   obs   = (const int*)d_in[0];
    const float* ST    = (const float*)d_in[1];
    const float* OT    = (const float*)d_in[2];
    const float* prior = (const float*)d_in[3];
    float* out = (float*)d_out;

    cudaFuncSetAttribute(k_forward, cudaFuncAttributeMaxDynamicSharedMemorySize,
                         SMEM_TOTAL);

    k_rowlse<<<S, 256>>>(ST);
    k_colmax<<<4, 128>>>(ST);
    k_pre3<<<S, 256>>>(ST, OT);
    k_forward<<<BATCH * 2, NTHREADS, SMEM_TOTAL>>>(obs, OT, prior, out);
}